// round 13
// baseline (speedup 1.0000x reference)
#include <cuda_runtime.h>
#include <cstdint>

// Embedding gather: out[token, :] = weight[input[token], :]
// input: [32768] int32, weight: [50257, 512] f32, out: [32768, 512] f32
//
// FINAL family. Twelve measured variants (MLP 1/4/8, TMA bulk, persistent
// grid, 256-bit v8 ops, every L2 cache-policy combination, 128/256-thread
// CTAs) all converge to 16.8-17.1us — the practical memory-system roofline
// for a random 2KB-row gather + 67MB streaming write (steady-state
// ~115MB/replay at ~6.85TB/s, ~85% of HBM spec).
//
// Structure = measured-best R5: one warp per token row, block's indices
// staged via ONE coalesced smem load (removes the dependent idx-LDG ->
// weight-LDG chain), 4 independent float4 loads per thread (MLP=4),
// __stcs evict-first streaming stores (best measured store policy).
// Last shape probe: 512-thread CTAs (16 warps) — better idx-load
// amortization, fewer barriers chip-wide.

#define WARPS_PER_CTA 16

__global__ __launch_bounds__(WARPS_PER_CTA * 32) void embed_gather_final16(
    const int* __restrict__ idx,
    const float4* __restrict__ weight4,
    float4* __restrict__ out4,
    int n_tokens)
{
    __shared__ int s_rows[WARPS_PER_CTA];

    const int tid  = threadIdx.x;
    const int warp = tid >> 5;
    const int lane = tid & 31;
    const int base = blockIdx.x * WARPS_PER_CTA;

    // One coalesced load fetches all 16 indices for this block.
    if (tid < WARPS_PER_CTA) {
        int t = base + tid;
        s_rows[tid] = (t < n_tokens) ? __ldg(idx + t) : 0;
    }
    __syncthreads();

    const int token = base + warp;
    if (token >= n_tokens) return;
    const int row = s_rows[warp];

    const float4* __restrict__ src = weight4 + (long long)row * 128 + lane;
    float4* __restrict__ dst       = out4    + (long long)token * 128 + lane;

    // 4 independent loads front-batched (MLP=4)
    float4 v0 = __ldg(src);
    float4 v1 = __ldg(src + 32);
    float4 v2 = __ldg(src + 64);
    float4 v3 = __ldg(src + 96);

    // Evict-first streaming writeback (measured best store policy).
    __stcs(dst,      v0);
    __stcs(dst + 32, v1);
    __stcs(dst + 64, v2);
    __stcs(dst + 96, v3);
}

extern "C" void kernel_launch(void* const* d_in, const int* in_sizes, int n_in,
                              void* d_out, int out_size) {
    const int*   idx    = (const int*)d_in[0];     // [8*4096] int32
    const float* weight = (const float*)d_in[1];   // [50257*512] f32
    float*       out    = (float*)d_out;

    int n_tokens = in_sizes[0];                    // 32768
    int blocks   = (n_tokens + WARPS_PER_CTA - 1) / WARPS_PER_CTA;  // 2048
    embed_gather_final16<<<blocks, WARPS_PER_CTA * 32>>>(
        idx, (const float4*)weight, (float4*)out, n_tokens);
}